// round 6
// baseline (speedup 1.0000x reference)
#include <cuda_runtime.h>
#include <math.h>
#include <stdint.h>

#define BB 16
#define NN 1024
#define DD 64
#define LOG2E 1.4426950408889634f
#define NSLAB 32           /* row slabs per batch in column pass */
#define SLABR (NN / NSLAB) /* 32 rows per slab */
#define GRID  512
#define TPB   256
#define NITER 50

// ---------------- scratch (static device globals; no allocations) ----------
__device__ float g_C[BB * NN * NN];        // C2 = -C * inv_eps * LOG2E  (<= 0)
__device__ float g_part[BB * NSLAB * NN];  // column partial sums (2 MB)
__device__ float g_x2[BB * NN];
__device__ float g_y2[BB * NN];
__device__ float g_Lu2[BB * NN];           // (log_u + cmin/eps) * LOG2E
__device__ float g_Lv2[BB * NN];           // (log_v + cmin/eps) * LOG2E
__device__ unsigned int g_cminbits[BB];
__device__ float g_inv_eps;

// global barrier state
__device__ unsigned int g_bar_count;
__device__ volatile unsigned int g_bar_gen;

// ---------------- helpers ---------------------------------------------------
__device__ __forceinline__ float ex2(float x) {
    float r;
    asm("ex2.approx.ftz.f32 %0, %1;" : "=f"(r) : "f"(x));
    return r;
}
__device__ __forceinline__ float lg2(float x) {
    float r;
    asm("lg2.approx.f32 %0, %1;" : "=f"(r) : "f"(x));
    return r;
}

__device__ __forceinline__ float read_eps(const void* p) {
    float f = *(const float*)p;
    if (isfinite(f) && fabsf(f) > 1e-20f && fabsf(f) < 1e20f) return f;
    return (float)(*(const int*)p);
}

// standard multi-block sync (all GRID blocks guaranteed co-resident)
__device__ __forceinline__ void grid_barrier() {
    __syncthreads();
    if (threadIdx.x == 0) {
        unsigned int gen = g_bar_gen;
        __threadfence();
        if (atomicAdd(&g_bar_count, 1u) == GRID - 1) {
            g_bar_count = 0;
            __threadfence();
            g_bar_gen = gen + 1;
        } else {
            while (g_bar_gen == gen) { }
            __threadfence();
        }
    }
    __syncthreads();
}

// ---------------- prep: x2, y2, eps, cmin init ------------------------------
__global__ void k_prep(const float* __restrict__ x, const float* __restrict__ y,
                       const void* __restrict__ epsp) {
    int idx = blockIdx.x * blockDim.x + threadIdx.x;
    if (idx == 0) g_inv_eps = 1.0f / read_eps(epsp);
    if (idx < BB) g_cminbits[idx] = 0x7F800000u;  // +inf
    if (idx < BB * NN) {
        const float4* xr = (const float4*)(x + (size_t)idx * DD);
        float s = 0.0f;
#pragma unroll
        for (int j = 0; j < DD / 4; j++) {
            float4 v = xr[j];
            s += v.x * v.x + v.y * v.y + v.z * v.z + v.w * v.w;
        }
        g_x2[idx] = s;
    } else if (idx < 2 * BB * NN) {
        int j2 = idx - BB * NN;
        const float4* yr = (const float4*)(y + (size_t)j2 * DD);
        float s = 0.0f;
#pragma unroll
        for (int j = 0; j < DD / 4; j++) {
            float4 v = yr[j];
            s += v.x * v.x + v.y * v.y + v.z * v.z + v.w * v.w;
        }
        g_y2[j2] = s;
    }
}

// ---------------- C2 = -max(x2+y2-2x.y,0)*inv_eps*LOG2E; track raw min ------
__global__ void k_gemm(const float* __restrict__ x, const float* __restrict__ y) {
    __shared__ float xs[64][65];
    __shared__ float ys[64][65];
    __shared__ float wmin[8];

    const int b  = blockIdx.z;
    const int n0 = blockIdx.y * 64;
    const int m0 = blockIdx.x * 64;
    const int t  = threadIdx.x;

    {
        int row = t >> 4;
        int col = (t & 15) * 4;
#pragma unroll
        for (int rr = 0; rr < 4; rr++) {
            int r = row + 16 * rr;
            float4 vx = *(const float4*)(x + ((size_t)(b * NN + n0 + r)) * DD + col);
            xs[r][col + 0] = vx.x; xs[r][col + 1] = vx.y;
            xs[r][col + 2] = vx.z; xs[r][col + 3] = vx.w;
            float4 vy = *(const float4*)(y + ((size_t)(b * NN + m0 + r)) * DD + col);
            ys[r][col + 0] = vy.x; ys[r][col + 1] = vy.y;
            ys[r][col + 2] = vy.z; ys[r][col + 3] = vy.w;
        }
    }
    __syncthreads();

    const int tn = t >> 4;
    const int tm = t & 15;
    float acc[4][4];
#pragma unroll
    for (int i = 0; i < 4; i++)
#pragma unroll
        for (int j = 0; j < 4; j++) acc[i][j] = 0.0f;

#pragma unroll 8
    for (int k = 0; k < 64; k++) {
        float a[4], bb_[4];
#pragma unroll
        for (int i = 0; i < 4; i++) a[i] = xs[tn * 4 + i][k];
#pragma unroll
        for (int j = 0; j < 4; j++) bb_[j] = ys[tm * 4 + j][k];
#pragma unroll
        for (int i = 0; i < 4; i++)
#pragma unroll
            for (int j = 0; j < 4; j++) acc[i][j] += a[i] * bb_[j];
    }

    const float negScale = -g_inv_eps * LOG2E;
    float tmin = INFINITY;
#pragma unroll
    for (int i = 0; i < 4; i++) {
        int n = n0 + tn * 4 + i;
        float xx = g_x2[b * NN + n];
        float4 cv;
        float c[4];
#pragma unroll
        for (int j = 0; j < 4; j++) {
            int m = m0 + tm * 4 + j;
            float v = xx + g_y2[b * NN + m] - 2.0f * acc[i][j];
            v = fmaxf(v, 0.0f);
            tmin = fminf(tmin, v);
            c[j] = v * negScale;
        }
        cv.x = c[0]; cv.y = c[1]; cv.z = c[2]; cv.w = c[3];
        *(float4*)(g_C + ((size_t)(b * NN + n)) * NN + m0 + tm * 4) = cv;
    }

#pragma unroll
    for (int off = 16; off > 0; off >>= 1)
        tmin = fminf(tmin, __shfl_xor_sync(0xFFFFFFFFu, tmin, off));
    if ((t & 31) == 0) wmin[t >> 5] = tmin;
    __syncthreads();
    if (t == 0) {
        float bm = wmin[0];
#pragma unroll
        for (int w = 1; w < 8; w++) bm = fminf(bm, wmin[w]);
        atomicMin(&g_cminbits[b], __float_as_uint(bm));
    }
}

// ---------------- persistent Sinkhorn loop -----------------------------------
// GRID=512 blocks x TPB=256 threads, all co-resident (<=4 blocks/SM via
// __launch_bounds__). Per iteration:
//   col phase:  block (b, slab) -> partial column sums over 32 rows (coalesced)
//   finv phase: block (b, m-chunk) -> combine 32 partials, update Lv2
//   row phase:  block (b, 32 rows), warp = 4 rows -> update Lu2
__global__ void __launch_bounds__(TPB, 4) k_sinkhorn() {
    __shared__ float sh[NN];          // row phase: Lv2; col phase: first 32 = Lu slab

    const int bid = blockIdx.x;
    const int t   = threadIdx.x;
    const int b   = bid >> 5;         // batch 0..15
    const int u5  = bid & 31;         // slab / row-block / m-chunk index

    // ---- init Lu2/Lv2 = cminv2 ----
    if (t < 32) {
        int idx = bid * 32 + t;
        int bb_ = idx >> 10;
        float cminv2 = __uint_as_float(g_cminbits[bb_]) * g_inv_eps * LOG2E;
        g_Lu2[idx] = cminv2;
        g_Lv2[idx] = cminv2;
    }
    const float cminv2 = __uint_as_float(g_cminbits[b]) * g_inv_eps * LOG2E;
    const float Cc = cminv2 - 10.0f;   // cminv2 - log2(1024)

    grid_barrier();

    for (int iter = 0; iter <= NITER; iter++) {
        // ======== column partial phase ========
        {
            const int n0 = u5 * SLABR;
            if (t < SLABR) sh[t] = g_Lu2[b * NN + n0 + t];

            float4 pl = *(const float4*)(g_Lv2 + b * NN + 4 * t);
            float4 V0;
            V0.x = Cc - pl.x; V0.y = Cc - pl.y;
            V0.z = Cc - pl.z; V0.w = Cc - pl.w;
            __syncthreads();

            const float4* Cp = (const float4*)(g_C + ((size_t)(b * NN + n0)) * NN) + t;
            float4 acc = make_float4(0.f, 0.f, 0.f, 0.f);
#pragma unroll 8
            for (int n = 0; n < SLABR; n++) {
                float4 c = Cp[n * (NN / 4)];
                float lu = sh[n];
                acc.x += ex2(c.x + lu - V0.x);
                acc.y += ex2(c.y + lu - V0.y);
                acc.z += ex2(c.z + lu - V0.z);
                acc.w += ex2(c.w + lu - V0.w);
            }
            ((float4*)(g_part + ((size_t)(b * NSLAB + u5)) * NN))[t] = acc;
        }
        grid_barrier();

        // ======== finv phase: combine partials -> Lv2 ========
        if (t < 32) {
            const int m = u5 * 32 + t;
            const float* P = g_part + (size_t)b * NSLAB * NN + m;
            float s = 0.0f;
#pragma unroll
            for (int p = 0; p < NSLAB; p++) s += P[p * NN];
            float V = Cc - g_Lv2[b * NN + m];       // old V0 used in col phase
            float LSE2 = V + lg2(fmaxf(s, 1e-38f));
            g_Lv2[b * NN + m] = Cc - LSE2;
        }
        grid_barrier();

        if (iter == NITER) break;

        // ======== row phase: update Lu2 ========
        {
            ((float4*)sh)[t] = ((const float4*)(g_Lv2 + b * NN))[t];
            __syncthreads();

            const int lane = t & 31;
            const int w    = t >> 5;       // warp 0..7
            const int r0   = u5 * 32 + w * 4;
            const float4* shv = (const float4*)sh;
#pragma unroll
            for (int rr = 0; rr < 4; rr++) {
                const int row = r0 + rr;
                const float V0 = Cc - g_Lu2[b * NN + row];
                const float4* Crow = (const float4*)(g_C + ((size_t)(b * NN + row)) * NN);
                float s0 = 0.f, s1 = 0.f, s2 = 0.f, s3 = 0.f;
#pragma unroll
                for (int j = 0; j < 8; j++) {
                    int i = lane + 32 * j;
                    float4 c = Crow[i];
                    float4 lv = shv[i];
                    s0 += ex2(c.x + lv.x - V0);
                    s1 += ex2(c.y + lv.y - V0);
                    s2 += ex2(c.z + lv.z - V0);
                    s3 += ex2(c.w + lv.w - V0);
                }
                float s = (s0 + s1) + (s2 + s3);
#pragma unroll
                for (int off = 16; off > 0; off >>= 1)
                    s += __shfl_down_sync(0xFFFFFFFFu, s, off);
                if (lane == 0) {
                    float LSE2 = V0 + lg2(fmaxf(s, 1e-38f));
                    g_Lu2[b * NN + row] = Cc - LSE2;
                }
            }
        }
        grid_barrier();
    }
}

// ---------------- output -----------------------------------------------------
// w[n,m] = exp2(C2[n,m] + Lu2[n] + Lv2[m] - cminv2); out = (w @ y) / rowsum(w)
__global__ void k_out(const float* __restrict__ y, float* __restrict__ out) {
    __shared__ __align__(16) float ysm[64 * 64];
    __shared__ __align__(16) float wt[16 * 64];

    const int b  = blockIdx.y;
    const int n0 = blockIdx.x * 16;
    const int t  = threadIdx.x;
    const int r  = t >> 4;
    const int dg = t & 15;

    const float cminv2 = __uint_as_float(g_cminbits[b]) * g_inv_eps * LOG2E;

    float4 acc = make_float4(0.f, 0.f, 0.f, 0.f);
    float wsum = 0.0f;

    for (int mt = 0; mt < NN; mt += 64) {
#pragma unroll
        for (int r2 = 0; r2 < 4; r2++) {
            int fid = t + 256 * r2;
            int row = fid >> 4;
            int col4 = fid & 15;
            ((float4*)ysm)[fid] =
                *(const float4*)(y + ((size_t)(b * NN + mt + row)) * DD + col4 * 4);
        }
        {
            int wid = t * 4;
            int rw = wid >> 6;
            int mmw = wid & 63;
            float4 cv = *(const float4*)(g_C + ((size_t)(b * NN + n0 + rw)) * NN + mt + mmw);
            float4 lv = *(const float4*)(g_Lv2 + b * NN + mt + mmw);
            float lu = g_Lu2[b * NN + n0 + rw] - cminv2;
            float4 wv;
            wv.x = ex2(cv.x + lv.x + lu);
            wv.y = ex2(cv.y + lv.y + lu);
            wv.z = ex2(cv.z + lv.z + lu);
            wv.w = ex2(cv.w + lv.w + lu);
            *(float4*)(wt + wid) = wv;
        }
        __syncthreads();

#pragma unroll 16
        for (int mm = 0; mm < 64; mm++) {
            float w = wt[r * 64 + mm];
            float4 yv = *(const float4*)(ysm + mm * 64 + dg * 4);
            acc.x += w * yv.x;
            acc.y += w * yv.y;
            acc.z += w * yv.z;
            acc.w += w * yv.w;
            wsum += w;
        }
        __syncthreads();
    }

    float rinv = 1.0f / fmaxf(wsum, 1e-12f);
    float4 o;
    o.x = acc.x * rinv; o.y = acc.y * rinv;
    o.z = acc.z * rinv; o.w = acc.w * rinv;
    *(float4*)(out + ((size_t)(b * NN + n0 + r)) * DD + dg * 4) = o;
}

// ---------------- launcher ---------------------------------------------------
extern "C" void kernel_launch(void* const* d_in, const int* in_sizes, int n_in,
                              void* d_out, int out_size) {
    const float* x = (const float*)d_in[0];
    const float* y = (const float*)d_in[1];
    const void* eps = d_in[2];
    float* out = (float*)d_out;

    k_prep<<<(2 * BB * NN + 255) / 256, 256>>>(x, y, eps);
    k_gemm<<<dim3(NN / 64, NN / 64, BB), 256>>>(x, y);
    k_sinkhorn<<<GRID, TPB>>>();
    k_out<<<dim3(NN / 16, BB), 256>>>(y, out);
}

// round 7
// speedup vs baseline: 1.6471x; 1.6471x over previous
#include <cuda_runtime.h>
#include <math.h>
#include <stdint.h>

#define BB 16
#define NN 1024
#define DD 64
#define LOG2E 1.4426950408889634f

// ---------------- scratch (static device globals; no allocations) ----------
__device__ float g_C[BB * NN * NN];   // C2 = -C * inv_eps * LOG2E  (<= 0)
__device__ float g_x2[BB * NN];
__device__ float g_y2[BB * NN];
__device__ float g_Lu2[BB * NN];      // (log_u + cmin/eps) * LOG2E
__device__ float g_Lv2[BB * NN];      // (log_v + cmin/eps) * LOG2E
__device__ unsigned int g_cminbits[BB];
__device__ float g_inv_eps;

// ---------------- helpers ---------------------------------------------------
__device__ __forceinline__ float ex2(float x) {
    float r;
    asm("ex2.approx.ftz.f32 %0, %1;" : "=f"(r) : "f"(x));
    return r;
}
__device__ __forceinline__ float lg2(float x) {
    float r;
    asm("lg2.approx.f32 %0, %1;" : "=f"(r) : "f"(x));
    return r;
}

__device__ __forceinline__ float read_eps(const void* p) {
    float f = *(const float*)p;
    if (isfinite(f) && fabsf(f) > 1e-20f && fabsf(f) < 1e20f) return f;
    return (float)(*(const int*)p);
}

// ---------------- prep: x2, y2, eps, cmin init ------------------------------
__global__ void k_prep(const float* __restrict__ x, const float* __restrict__ y,
                       const void* __restrict__ epsp) {
    int idx = blockIdx.x * blockDim.x + threadIdx.x;
    if (idx == 0) g_inv_eps = 1.0f / read_eps(epsp);
    if (idx < BB) g_cminbits[idx] = 0x7F800000u;  // +inf
    if (idx < BB * NN) {
        const float4* xr = (const float4*)(x + (size_t)idx * DD);
        float s = 0.0f;
#pragma unroll
        for (int j = 0; j < DD / 4; j++) {
            float4 v = xr[j];
            s += v.x * v.x + v.y * v.y + v.z * v.z + v.w * v.w;
        }
        g_x2[idx] = s;
    } else if (idx < 2 * BB * NN) {
        int j2 = idx - BB * NN;
        const float4* yr = (const float4*)(y + (size_t)j2 * DD);
        float s = 0.0f;
#pragma unroll
        for (int j = 0; j < DD / 4; j++) {
            float4 v = yr[j];
            s += v.x * v.x + v.y * v.y + v.z * v.z + v.w * v.w;
        }
        g_y2[j2] = s;
    }
}

// ---------------- C2 = -max(x2+y2-2x.y,0)*inv_eps*LOG2E; track raw min ------
__global__ void k_gemm(const float* __restrict__ x, const float* __restrict__ y) {
    __shared__ float xs[64][65];
    __shared__ float ys[64][65];
    __shared__ float wmin[8];

    const int b  = blockIdx.z;
    const int n0 = blockIdx.y * 64;
    const int m0 = blockIdx.x * 64;
    const int t  = threadIdx.x;

    {
        int row = t >> 4;
        int col = (t & 15) * 4;
#pragma unroll
        for (int rr = 0; rr < 4; rr++) {
            int r = row + 16 * rr;
            float4 vx = *(const float4*)(x + ((size_t)(b * NN + n0 + r)) * DD + col);
            xs[r][col + 0] = vx.x; xs[r][col + 1] = vx.y;
            xs[r][col + 2] = vx.z; xs[r][col + 3] = vx.w;
            float4 vy = *(const float4*)(y + ((size_t)(b * NN + m0 + r)) * DD + col);
            ys[r][col + 0] = vy.x; ys[r][col + 1] = vy.y;
            ys[r][col + 2] = vy.z; ys[r][col + 3] = vy.w;
        }
    }
    __syncthreads();

    const int tn = t >> 4;
    const int tm = t & 15;
    float acc[4][4];
#pragma unroll
    for (int i = 0; i < 4; i++)
#pragma unroll
        for (int j = 0; j < 4; j++) acc[i][j] = 0.0f;

#pragma unroll 8
    for (int k = 0; k < 64; k++) {
        float a[4], bb_[4];
#pragma unroll
        for (int i = 0; i < 4; i++) a[i] = xs[tn * 4 + i][k];
#pragma unroll
        for (int j = 0; j < 4; j++) bb_[j] = ys[tm * 4 + j][k];
#pragma unroll
        for (int i = 0; i < 4; i++)
#pragma unroll
            for (int j = 0; j < 4; j++) acc[i][j] += a[i] * bb_[j];
    }

    const float negScale = -g_inv_eps * LOG2E;
    float tmin = INFINITY;
#pragma unroll
    for (int i = 0; i < 4; i++) {
        int n = n0 + tn * 4 + i;
        float xx = g_x2[b * NN + n];
        float4 cv;
        float c[4];
#pragma unroll
        for (int j = 0; j < 4; j++) {
            int m = m0 + tm * 4 + j;
            float v = xx + g_y2[b * NN + m] - 2.0f * acc[i][j];
            v = fmaxf(v, 0.0f);
            tmin = fminf(tmin, v);
            c[j] = v * negScale;
        }
        cv.x = c[0]; cv.y = c[1]; cv.z = c[2]; cv.w = c[3];
        *(float4*)(g_C + ((size_t)(b * NN + n)) * NN + m0 + tm * 4) = cv;
    }

#pragma unroll
    for (int off = 16; off > 0; off >>= 1)
        tmin = fminf(tmin, __shfl_xor_sync(0xFFFFFFFFu, tmin, off));
    if ((t & 31) == 0) wmin[t >> 5] = tmin;
    __syncthreads();
    if (t == 0) {
        float bm = wmin[0];
#pragma unroll
        for (int w = 1; w < 8; w++) bm = fminf(bm, wmin[w]);
        atomicMin(&g_cminbits[b], __float_as_uint(bm));
    }
}

// ---------------- init Lu2/Lv2 = cmin*inv_eps*LOG2E (log_u = log_v = 0) -----
__global__ void k_init() {
    int idx = blockIdx.x * blockDim.x + threadIdx.x;
    if (idx < BB * NN) {
        int b = idx >> 10;
        float cminv2 = __uint_as_float(g_cminbits[b]) * g_inv_eps * LOG2E;
        g_Lu2[idx] = cminv2;
        g_Lv2[idx] = cminv2;
    }
}

// ---------------- column pass ------------------------------------------------
// Lv2_new[m] = Cv - (V0 + log2(sum_n exp2(C2[n,m] + Lu2[n] - V0)))
// Block: 64 columns x full 1024 rows. 512 threads = 16 col-groups(x4) x 32 row parts.
__global__ void __launch_bounds__(512) k_col() {
    __shared__ float lu2s[NN];
    __shared__ float4 part[32][16];

    const int b  = blockIdx.y;
    const int m0 = blockIdx.x * 64;
    const int t  = threadIdx.x;
    const int g  = t & 15;   // column group (4 cols)
    const int p  = t >> 4;   // row partition (32 rows)

    lu2s[t]       = g_Lu2[b * NN + t];
    lu2s[t + 512] = g_Lu2[b * NN + t + 512];

    const float cminv2 = __uint_as_float(g_cminbits[b]) * g_inv_eps * LOG2E;
    const float Cv = cminv2 - 10.0f;   // - log2(1024)

    float4 pl = *(const float4*)(g_Lv2 + b * NN + m0 + 4 * g);
    float4 V0;
    V0.x = Cv - pl.x; V0.y = Cv - pl.y; V0.z = Cv - pl.z; V0.w = Cv - pl.w;
    __syncthreads();

    const float4* Cp = (const float4*)(g_C + (size_t)b * NN * NN) + (m0 >> 2) + g;
    float s0 = 0.f, s1 = 0.f, s2 = 0.f, s3 = 0.f;
    const int nbeg = p * 32;
#pragma unroll 4
    for (int n = nbeg; n < nbeg + 32; n++) {
        float4 c = Cp[(size_t)n * (NN / 4)];
        float lu = lu2s[n];
        s0 += ex2(c.x + lu - V0.x);
        s1 += ex2(c.y + lu - V0.y);
        s2 += ex2(c.z + lu - V0.z);
        s3 += ex2(c.w + lu - V0.w);
    }
    part[p][g] = make_float4(s0, s1, s2, s3);
    __syncthreads();

    if (t < 64) {
        int gg = t >> 2, j = t & 3;
        float s = 0.0f;
#pragma unroll
        for (int q = 0; q < 32; q++) s += ((const float*)&part[q][gg])[j];
        float V = Cv - g_Lv2[b * NN + m0 + t];   // same (old) V0 for this column
        float LSE2 = V + lg2(fmaxf(s, 1e-38f));
        g_Lv2[b * NN + m0 + t] = Cv - LSE2;
    }
}

// ---------------- row pass ---------------------------------------------------
// Lu2_new[n] = Cu - (V0 + log2(sum_m exp2(C2[n,m] + Lv2[m] - V0)))
// 256 threads = 8 warps, warp per row.
__global__ void k_row() {
    __shared__ float4 lv2s[NN / 4];

    const int b = blockIdx.y;
    const int t = threadIdx.x;
    const int lane = t & 31;
    const int row  = blockIdx.x * 8 + (t >> 5);

    lv2s[t] = ((const float4*)(g_Lv2 + b * NN))[t];

    const float cminv2 = __uint_as_float(g_cminbits[b]) * g_inv_eps * LOG2E;
    const float Cu = cminv2 - 10.0f;
    const float V0 = Cu - g_Lu2[b * NN + row];
    __syncthreads();

    const float4* Crow = (const float4*)(g_C + ((size_t)(b * NN + row)) * NN);
    float s0 = 0.f, s1 = 0.f, s2 = 0.f, s3 = 0.f;
#pragma unroll
    for (int j = 0; j < 8; j++) {
        int i = lane + 32 * j;
        float4 c = Crow[i];
        float4 lv = lv2s[i];
        s0 += ex2(c.x + lv.x - V0);
        s1 += ex2(c.y + lv.y - V0);
        s2 += ex2(c.z + lv.z - V0);
        s3 += ex2(c.w + lv.w - V0);
    }
    float s = (s0 + s1) + (s2 + s3);
#pragma unroll
    for (int off = 16; off > 0; off >>= 1)
        s += __shfl_down_sync(0xFFFFFFFFu, s, off);
    if (lane == 0) {
        float LSE2 = V0 + lg2(fmaxf(s, 1e-38f));
        g_Lu2[b * NN + row] = Cu - LSE2;
    }
}

// ---------------- output -----------------------------------------------------
// w[n,m] = exp2(C2[n,m] + Lu2[n] + Lv2[m] - cminv2); out = (w @ y) / rowsum(w)
// wt padded to stride 65: bank(r,mm) = (r + mm) mod 32 -> 16 distinct r are
// conflict-free for the inner-loop read.
__global__ void k_out(const float* __restrict__ y, float* __restrict__ out) {
    __shared__ __align__(16) float ysm[64 * 64];
    __shared__ float wt[16 * 65];

    const int b  = blockIdx.y;
    const int n0 = blockIdx.x * 16;
    const int t  = threadIdx.x;
    const int r  = t >> 4;
    const int dg = t & 15;

    const float cminv2 = __uint_as_float(g_cminbits[b]) * g_inv_eps * LOG2E;

    float4 acc = make_float4(0.f, 0.f, 0.f, 0.f);
    float wsum = 0.0f;

    for (int mt = 0; mt < NN; mt += 64) {
#pragma unroll
        for (int r2 = 0; r2 < 4; r2++) {
            int fid = t + 256 * r2;
            int row = fid >> 4;
            int col4 = fid & 15;
            ((float4*)ysm)[fid] =
                *(const float4*)(y + ((size_t)(b * NN + mt + row)) * DD + col4 * 4);
        }
        {
            int wid = t * 4;
            int rw = wid >> 6;
            int mmw = wid & 63;
            float4 cv = *(const float4*)(g_C + ((size_t)(b * NN + n0 + rw)) * NN + mt + mmw);
            float4 lv = *(const float4*)(g_Lv2 + b * NN + mt + mmw);
            float lu = g_Lu2[b * NN + n0 + rw] - cminv2;
            wt[rw * 65 + mmw + 0] = ex2(cv.x + lv.x + lu);
            wt[rw * 65 + mmw + 1] = ex2(cv.y + lv.y + lu);
            wt[rw * 65 + mmw + 2] = ex2(cv.z + lv.z + lu);
            wt[rw * 65 + mmw + 3] = ex2(cv.w + lv.w + lu);
        }
        __syncthreads();

#pragma unroll 16
        for (int mm = 0; mm < 64; mm++) {
            float w = wt[r * 65 + mm];
            float4 yv = *(const float4*)(ysm + mm * 64 + dg * 4);
            acc.x += w * yv.x;
            acc.y += w * yv.y;
            acc.z += w * yv.z;
            acc.w += w * yv.w;
            wsum += w;
        }
        __syncthreads();
    }

    float rinv = 1.0f / fmaxf(wsum, 1e-12f);
    float4 o;
    o.x = acc.x * rinv; o.y = acc.y * rinv;
    o.z = acc.z * rinv; o.w = acc.w * rinv;
    *(float4*)(out + ((size_t)(b * NN + n0 + r)) * DD + dg * 4) = o;
}

// ---------------- launcher ---------------------------------------------------
extern "C" void kernel_launch(void* const* d_in, const int* in_sizes, int n_in,
                              void* d_out, int out_size) {
    const float* x = (const float*)d_in[0];
    const float* y = (const float*)d_in[1];
    const void* eps = d_in[2];
    float* out = (float*)d_out;

    k_prep<<<(2 * BB * NN + 255) / 256, 256>>>(x, y, eps);
    k_gemm<<<dim3(NN / 64, NN / 64, BB), 256>>>(x, y);
    k_init<<<(BB * NN + 255) / 256, 256>>>();

    for (int it = 0; it < 50; it++) {
        k_col<<<dim3(NN / 64, BB), 512>>>();
        k_row<<<dim3(NN / 8, BB), 256>>>();
    }
    k_col<<<dim3(NN / 64, BB), 512>>>();  // final v-update

    k_out<<<dim3(NN / 16, BB), 256>>>(y, out);
}